// round 16
// baseline (speedup 1.0000x reference)
#include <cuda_runtime.h>
#include <cuda_fp16.h>
#include <cstdint>

// ============================================================
// RankingLoss: persistent fp16 mma.sync (f16 accumulate) GEMM,
// 1024-thread CTAs, cp.async ring, fused hinge epilogue +
// in-kernel final reduce. gt exact fp32.
// loss = sum_{b,c: tc[c]!=label[b]} max(1 + pred_b·sigc_c - gt_b, 0)
// ============================================================

#define MAX_B   16384
#define DDIM    256
#define CPAD    2048
#define PGRID   148

__device__ float g_gt[MAX_B];
__device__ float g_partial[CPAD];
__device__ float g_sigT[CPAD * DDIM];             // sig^T fp32 [c][d]
__device__ __half g_predh[MAX_B * DDIM];          // pred fp16 [b][d]
__device__ __half g_sgath[CPAD * DDIM];           // gathered sig fp16 [c][d]
__device__ int g_tcs[CPAD];                        // class ids (-1 pad)
__device__ unsigned g_done;

// ---------------- transpose sig fp32: [d][c] -> [c][d], slab version ----------------
// grid (63, 2): block = 32-class slab x 128-d half; 4 staged 32x32 tiles.
__global__ void transpose_sig_kernel(const float* __restrict__ sig, int C) {
    __shared__ float t[32][33];
    const int cb = blockIdx.x * 32;
    const int tx = threadIdx.x & 31, ty = threadIdx.x >> 5;   // 256 thr, ty 0..7
    #pragma unroll
    for (int dt = 0; dt < 4; dt++) {
        int db = blockIdx.y * 128 + dt * 32;
        #pragma unroll
        for (int i = 0; i < 32; i += 8) {
            int d = db + ty + i, c = cb + tx;
            t[ty + i][tx] = (c < C) ? sig[(size_t)d * C + c] : 0.f;
        }
        __syncthreads();
        #pragma unroll
        for (int i = 0; i < 32; i += 8) {
            int c = cb + ty + i, d = db + tx;
            if (c < C) g_sigT[(size_t)c * DDIM + d] = t[tx][ty + i];
        }
        __syncthreads();
    }
    if (blockIdx.x == 0 && blockIdx.y == 0 && threadIdx.x == 0) g_done = 0u;
}

// ---------------- fused prep: pred->fp16 + gt (rows); gathered sig->fp16 (classes) ----------------
__device__ __forceinline__ uint4 cvt8_h(float4 a, float4 b) {
    __half2 o[4];
    o[0] = __floats2half2_rn(a.x, a.y);
    o[1] = __floats2half2_rn(a.z, a.w);
    o[2] = __floats2half2_rn(b.x, b.y);
    o[3] = __floats2half2_rn(b.z, b.w);
    return *(uint4*)o;
}

__global__ void prep_all_kernel(const float* __restrict__ pred,
                                const int* __restrict__ label,
                                const int* __restrict__ tclass,
                                int B, int C) {
    const int tid = threadIdx.x, lane = tid & 31, wid = tid >> 5;
    const int rowBlocks = B / 8;

    if ((int)blockIdx.x < rowBlocks) {
        int b = blockIdx.x * 8 + wid;
        const float4* p4 = (const float4*)pred + (size_t)b * 64;
        float4 v0 = p4[lane * 2], v1 = p4[lane * 2 + 1];
        *(uint4*)&g_predh[(size_t)b * DDIM + lane * 8] = cvt8_h(v0, v1);
        int lb = label[b];
        const float4* s4 = (const float4*)g_sigT + (size_t)lb * 64;
        float4 c0 = s4[lane * 2], c1 = s4[lane * 2 + 1];
        float s = v0.x*c0.x + v0.y*c0.y + v0.z*c0.z + v0.w*c0.w
                + v1.x*c1.x + v1.y*c1.y + v1.z*c1.z + v1.w*c1.w;
        #pragma unroll
        for (int o = 16; o > 0; o >>= 1) s += __shfl_down_sync(0xffffffffu, s, o);
        if (lane == 0) g_gt[b] = s;
    } else {
        int c = ((int)blockIdx.x - rowBlocks) * 8 + wid;
        if (c < C) {
            int cls = tclass[c];
            const float4* s4 = (const float4*)g_sigT + (size_t)cls * 64;
            float4 v0 = s4[lane * 2], v1 = s4[lane * 2 + 1];
            *(uint4*)&g_sgath[(size_t)c * DDIM + lane * 8] = cvt8_h(v0, v1);
            if (lane == 0) g_tcs[c] = cls;
        } else if (c < CPAD) {
            uint4 z; z.x = z.y = z.z = z.w = 0u;
            *(uint4*)&g_sgath[(size_t)c * DDIM + lane * 8] = z;
            if (lane == 0) g_tcs[c] = -1;
        }
    }
}

// ---------------- persistent fp16 MMA GEMM + hinge + final reduce ----------------
// Tile: 128 rows x 256 classes. 1024 threads (32 warps, 8m x 4n, warp 16x64).
// Ring: 4 slots x (A 16KB + B 32KB) = 192KB.
#define SLOT_SZ  49152
#define B_SUB    16384
#define RED_OFF  196608
#define SMEM_TOTAL 200704

__device__ __forceinline__ uint32_t smem_u32(const void* p) {
    uint32_t a;
    asm("{ .reg .u64 t; cvta.to.shared.u64 t, %1; cvt.u32.u64 %0, t; }" : "=r"(a) : "l"(p));
    return a;
}

#define CP_ASYNC16(dst, src) \
    asm volatile("cp.async.cg.shared.global [%0], [%1], 16;" :: "r"(dst), "l"(src) : "memory")
#define CP_COMMIT() asm volatile("cp.async.commit_group;" ::: "memory")
#define CP_WAIT2()  asm volatile("cp.async.wait_group 2;" ::: "memory")

#define LDMX4(r0, r1, r2, r3, a) \
    asm volatile("ldmatrix.sync.aligned.m8n8.x4.shared.b16 {%0,%1,%2,%3}, [%4];" \
        : "=r"(r0), "=r"(r1), "=r"(r2), "=r"(r3) : "r"(a))

// fp16-accumulate MMA: D/C are 2 regs (4 halves)
#define MMAF16(c, A, b0, b1) \
    asm volatile("mma.sync.aligned.m16n8k16.row.col.f16.f16.f16.f16 " \
        "{%0,%1}, {%2,%3,%4,%5}, {%6,%7}, {%0,%1};" \
        : "+r"((c)[0]), "+r"((c)[1]) \
        : "r"((A)[0]), "r"((A)[1]), "r"((A)[2]), "r"((A)[3]), "r"(b0), "r"(b1))

// Fill one 64-k chunk of tile (ft) into ring slot fc. 1024 threads.
__device__ __forceinline__ void fill_chunk(uint32_t sb, int ft, int fc, int tid) {
    const int r0f = (ft >> 3) * 128;
    const int c0f = (ft & 7) * 256;
    const uint32_t slot = sb + (uint32_t)fc * SLOT_SZ;
    {   // A: 128 rows x 8 units = 1024 ops
        int row = tid >> 3, u = tid & 7;
        uint32_t dst = slot + (uint32_t)row * 128u + (uint32_t)((u ^ (row & 7)) << 4);
        size_t src = __cvta_generic_to_global(&g_predh[(size_t)(r0f + row) * DDIM + fc * 64 + u * 8]);
        CP_ASYNC16(dst, src);
    }
    #pragma unroll
    for (int i = 0; i < 2; i++) {              // B: 256 rows x 8 units = 2048 ops
        int op = tid + i * 1024;
        int row = op >> 3, u = op & 7;
        uint32_t dst = slot + B_SUB + (uint32_t)row * 128u + (uint32_t)((u ^ (row & 7)) << 4);
        size_t src = __cvta_generic_to_global(&g_sgath[(size_t)(c0f + row) * DDIM + fc * 64 + u * 8]);
        CP_ASYNC16(dst, src);
    }
}

__global__ __launch_bounds__(1024, 1)
void hinge_mma_kernel(const int* __restrict__ label, int nt, float* __restrict__ out) {
    extern __shared__ char smem[];
    const uint32_t sb = smem_u32(smem);
    const int tid = threadIdx.x, lane = tid & 31, wid = tid >> 5;
    const int bid = blockIdx.x;

    const int wm = (wid & 7) * 16;             // warp 16 rows
    const int wn = (wid >> 3) * 64;            // warp 64 cols
    const int lrow = lane & 15;
    const uint32_t u0 = (uint32_t)(lane >> 4);
    const uint32_t xr = (uint32_t)(lane & 7);

    uint32_t acc[8][2];                        // fp16x2 accumulators
    #pragma unroll
    for (int ni = 0; ni < 8; ni++) { acc[ni][0] = 0u; acc[ni][1] = 0u; }

    // ---- pipeline prologue: fill 3 chunks ahead ----
    int ft = bid, fc = 0;
    #pragma unroll
    for (int p = 0; p < 3; p++) {
        if (ft < nt) fill_chunk(sb, ft, fc, tid);
        CP_COMMIT();
        if (++fc == 4) { fc = 0; ft += PGRID; }
    }

    for (int tile = bid; tile < nt; tile += PGRID) {
        #pragma unroll
        for (int ch = 0; ch < 4; ch++) {
            CP_WAIT2();
            __syncthreads();
            if (ft < nt) fill_chunk(sb, ft, fc, tid);
            CP_COMMIT();
            if (++fc == 4) { fc = 0; ft += PGRID; }
            // ---- MMA on chunk ch (4 k-steps) ----
            const uint32_t slot = sb + (uint32_t)ch * SLOT_SZ;
            const uint32_t baseA = slot + (uint32_t)(wm + lrow) * 128u;
            const uint32_t baseB = slot + B_SUB + (uint32_t)(wn + lrow) * 128u;
            #pragma unroll
            for (int kk = 0; kk < 4; kk++) {
                const uint32_t t = (((uint32_t)(2 * kk) + u0) ^ xr) << 4;
                uint32_t a[4];
                LDMX4(a[0], a[1], a[2], a[3], baseA + t);
                #pragma unroll
                for (int p = 0; p < 4; p++) {
                    uint32_t q0, q1, q2, q3;
                    LDMX4(q0, q1, q2, q3, baseB + (uint32_t)p * 2048u + t);
                    MMAF16(acc[2 * p], a, q0, q2);
                    MMAF16(acc[2 * p + 1], a, q1, q3);
                }
            }
        }

        // ---- fused hinge epilogue ----
        const int r0 = (tile >> 3) * 128;
        const int c0 = (tile & 7) * 256;
        float lsum = 0.f;
        #pragma unroll
        for (int half = 0; half < 2; half++) {
            const int r = r0 + wm + (lane >> 2) + half * 8;
            const float base = 1.0f - g_gt[r];
            const int lb = __ldg(&label[r]);
            #pragma unroll
            for (int ni = 0; ni < 8; ni++) {
                const int cb = c0 + wn + ni * 8 + (lane & 3) * 2;
                const int cls0 = g_tcs[cb], cls1 = g_tcs[cb + 1];
                float2 f = __half22float2(*(__half2*)&acc[ni][half]);
                if (cls0 >= 0 && cls0 != lb) lsum += fmaxf(f.x + base, 0.f);
                if (cls1 >= 0 && cls1 != lb) lsum += fmaxf(f.y + base, 0.f);
                acc[ni][half] = 0u;
            }
        }
        #pragma unroll
        for (int o = 16; o > 0; o >>= 1) lsum += __shfl_down_sync(0xffffffffu, lsum, o);
        float* red = (float*)(smem + RED_OFF);
        if (lane == 0) red[wid] = lsum;
        __syncthreads();
        if (tid < 32) {
            float v = red[tid];
            #pragma unroll
            for (int o = 16; o > 0; o >>= 1) v += __shfl_down_sync(0xffffffffu, v, o);
            if (tid == 0) g_partial[tile] = v;
        }
        __syncthreads();
    }

    // ---- last CTA: deterministic final reduction ----
    float* red = (float*)(smem + RED_OFF);
    __threadfence();
    if (tid == 0) {
        unsigned v = atomicAdd(&g_done, 1u);
        ((unsigned*)red)[0] = (v == (unsigned)gridDim.x - 1u) ? 1u : 0u;
    }
    __syncthreads();
    if (((unsigned*)red)[0]) {
        float s = 0.f;
        for (int i = tid; i < nt; i += 1024) s += g_partial[i];
        __syncthreads();
        red[tid] = s;
        __syncthreads();
        #pragma unroll
        for (int o = 512; o > 0; o >>= 1) {
            if (tid < o) red[tid] += red[tid + o];
            __syncthreads();
        }
        if (tid == 0) out[0] = red[0];
    }
}

extern "C" void kernel_launch(void* const* d_in, const int* in_sizes, int n_in,
                              void* d_out, int out_size) {
    const float* pred   = (const float*)d_in[0];
    const int*   label  = (const int*)d_in[1];
    const int*   tclass = (const int*)d_in[2];
    const float* sig    = (const float*)d_in[3];
    float* out = (float*)d_out;

    const int B = in_sizes[1];
    const int C = in_sizes[2];

    {
        dim3 tg((C + 31) / 32, 2);
        transpose_sig_kernel<<<tg, 256>>>(sig, C);
    }
    prep_all_kernel<<<B / 8 + CPAD / 8, 256>>>(pred, label, tclass, B, C);

    const int nt = (CPAD / 256) * (B / 128);
    cudaFuncSetAttribute(hinge_mma_kernel, cudaFuncAttributeMaxDynamicSharedMemorySize, SMEM_TOTAL);
    hinge_mma_kernel<<<PGRID, 1024, SMEM_TOTAL>>>(label, nt, out);
}